// round 12
// baseline (speedup 1.0000x reference)
#include <cuda_runtime.h>
#include <cuda_fp16.h>
#include <cuda_bf16.h>
#include <cstdint>
#include <cstddef>

// ---------------------------------------------------------------------------
// Problem constants
// ---------------------------------------------------------------------------
#define LEN   13294          // 100*100 + 50*50 + 25*25 + 13*13
#define BATCH 2
#define TOK   (BATCH * LEN)  // 26588
#define NHEAD  8
#define LN_EPS 1e-5f

#define SZ256  ((size_t)TOK * 256)
#define SZ128  ((size_t)TOK * 128)
#define SZ1024 ((size_t)TOK * 1024)

#define NPERSIST 296         // 148 SMs x 2 CTAs/SM

__device__ float g_scratch[7 * SZ256 + SZ128 + SZ1024];

// ---------------------------------------------------------------------------
// Elementwise add
// ---------------------------------------------------------------------------
__global__ void add_kernel(const float* __restrict__ a, const float* __restrict__ b,
                           float* __restrict__ c, int n4) {
    int i = blockIdx.x * blockDim.x + threadIdx.x;
    if (i >= n4) return;
    float4 va = ((const float4*)a)[i];
    float4 vb = ((const float4*)b)[i];
    ((float4*)c)[i] = make_float4(va.x + vb.x, va.y + vb.y, va.z + vb.z, va.w + vb.w);
}

// ---------------------------------------------------------------------------
// cp.async helpers
// ---------------------------------------------------------------------------
__device__ __forceinline__ void cp_async16(void* smem, const void* gmem, bool pred) {
    uint32_t s = (uint32_t)__cvta_generic_to_shared(smem);
    int sz = pred ? 16 : 0;
    asm volatile("cp.async.cg.shared.global [%0], [%1], 16, %2;\n"
                 :: "r"(s), "l"(gmem), "r"(sz));
}
__device__ __forceinline__ void cp_commit() {
    asm volatile("cp.async.commit_group;\n" ::);
}
template <int N>
__device__ __forceinline__ void cp_wait() {
    asm volatile("cp.async.wait_group %0;\n" :: "n"(N));
}

#define MMA_TF32(d, a, b)                                                     \
    asm volatile(                                                             \
        "mma.sync.aligned.m16n8k8.row.col.f32.tf32.tf32.f32 "                 \
        "{%0,%1,%2,%3},{%4,%5,%6,%7},{%8,%9},{%0,%1,%2,%3};"                  \
        : "+f"(d[0]), "+f"(d[1]), "+f"(d[2]), "+f"(d[3])                      \
        : "r"(a[0]), "r"(a[1]), "r"(a[2]), "r"(a[3]), "r"(b[0]), "r"(b[1]))

// ---------------------------------------------------------------------------
// TF32 tensor-core GEMM, 4-stage cp.async pipeline + fragment double-buffer,
// PERSISTENT tile loop (grid = NPERSIST CTAs, each walks tiles with stride).
// Block tile 128x128, BK=16, 256 threads (8 warps), warp tile 64x32.
// ---------------------------------------------------------------------------
#define AS_STRIDE 20    // 16 + 4 pad
#define BS_STRIDE 136   // 128 + 8 pad
#define STAGES 4
#define AS_ELEMS (128 * AS_STRIDE)
#define BS_ELEMS (16 * BS_STRIDE)
#define GEMM_SMEM_BYTES (STAGES * (AS_ELEMS + BS_ELEMS) * 4)   // 75,776

__device__ __forceinline__ void load_frag_a(uint32_t (&a)[4][4], const float* asb,
                                            int wm, int g, int tg, int kk) {
    #pragma unroll
    for (int mi = 0; mi < 4; ++mi) {
        int base = (wm + mi * 16 + g) * AS_STRIDE + kk + tg;
        a[mi][0] = __float_as_uint(asb[base]);
        a[mi][1] = __float_as_uint(asb[base + 8 * AS_STRIDE]);
        a[mi][2] = __float_as_uint(asb[base + 4]);
        a[mi][3] = __float_as_uint(asb[base + 8 * AS_STRIDE + 4]);
    }
}
__device__ __forceinline__ void load_frag_b(uint32_t (&b)[4][2], const float* bsb,
                                            int wn, int g, int tg, int kk) {
    #pragma unroll
    for (int ni = 0; ni < 4; ++ni) {
        int c = wn + ni * 8 + g;
        b[ni][0] = __float_as_uint(bsb[(kk + tg) * BS_STRIDE + c]);
        b[ni][1] = __float_as_uint(bsb[(kk + tg + 4) * BS_STRIDE + c]);
    }
}

template <bool RELU, typename OutT>
__global__ __launch_bounds__(256, 2) void gemm_tc(
    const float* __restrict__ A, const float* __restrict__ W,
    const float* __restrict__ bias, const float* __restrict__ res,
    OutT* __restrict__ C, int M, int N, int K, int nbx, int ntiles)
{
    extern __shared__ float smem[];
    float* AsBase = smem;
    float* BsBase = smem + STAGES * AS_ELEMS;

    const int tid = threadIdx.x;
    const int wid = tid >> 5, lane = tid & 31;
    const int wm = (wid & 1) * 64;
    const int wn = (wid >> 1) * 32;
    const int g = lane >> 2, tg = lane & 3;

    const int arow = tid >> 1;            // 0..127
    const int acol = (tid & 1) * 8;       // 0 or 8
    const int brow = tid >> 4;            // 0..15
    const int bcol = (tid & 15) * 8;      // 0..120

    const int nst = K >> 4;

    for (int t = blockIdx.x; t < ntiles; t += NPERSIST) {
        const int bm = (t / nbx) * 128;
        const int bn = (t % nbx) * 128;
        const bool aok = (bm + arow) < M;
        const float* Ap = A + (size_t)(bm + arow) * K + acol;
        const float* Bp = W + (size_t)brow * N + bn + bcol;

        // prologue: issue stages 0..STAGES-2
        #pragma unroll
        for (int s = 0; s < STAGES - 1; ++s) {
            const int k0 = s << 4;
            float* as = AsBase + s * AS_ELEMS;
            float* bs = BsBase + s * BS_ELEMS;
            cp_async16(&as[arow * AS_STRIDE + acol],     Ap + k0,     aok);
            cp_async16(&as[arow * AS_STRIDE + acol + 4], Ap + k0 + 4, aok);
            const float* bp = Bp + (size_t)k0 * N;
            cp_async16(&bs[brow * BS_STRIDE + bcol],     bp,     true);
            cp_async16(&bs[brow * BS_STRIDE + bcol + 4], bp + 4, true);
            cp_commit();
        }

        float acc[4][4][4];
        #pragma unroll
        for (int mi = 0; mi < 4; ++mi)
            #pragma unroll
            for (int ni = 0; ni < 4; ++ni)
                #pragma unroll
                for (int e = 0; e < 4; ++e) acc[mi][ni][e] = 0.f;

        uint32_t fa[2][4][4], fb[2][4][2];

        cp_wait<1>();
        __syncthreads();
        load_frag_a(fa[0], AsBase, wm, g, tg, 0);
        load_frag_b(fb[0], BsBase, wn, g, tg, 0);

        for (int s = 0; s < nst; ++s) {
            // issue stage s+3 into buf (s+3)%4 = (s-1)%4
            {
                const int sn = s + STAGES - 1;
                if (sn < nst) {
                    const int buf = sn & (STAGES - 1);
                    const int k0 = sn << 4;
                    float* as = AsBase + buf * AS_ELEMS;
                    float* bs = BsBase + buf * BS_ELEMS;
                    cp_async16(&as[arow * AS_STRIDE + acol],     Ap + k0,     aok);
                    cp_async16(&as[arow * AS_STRIDE + acol + 4], Ap + k0 + 4, aok);
                    const float* bp = Bp + (size_t)k0 * N;
                    cp_async16(&bs[brow * BS_STRIDE + bcol],     bp,     true);
                    cp_async16(&bs[brow * BS_STRIDE + bcol + 4], bp + 4, true);
                }
                cp_commit();
            }

            const float* asb = AsBase + (s & (STAGES - 1)) * AS_ELEMS;
            const float* bsb = BsBase + (s & (STAGES - 1)) * BS_ELEMS;

            // prefetch kk=8 frags while computing kk=0
            load_frag_a(fa[1], asb, wm, g, tg, 8);
            load_frag_b(fb[1], bsb, wn, g, tg, 8);
            #pragma unroll
            for (int mi = 0; mi < 4; ++mi)
                #pragma unroll
                for (int ni = 0; ni < 4; ++ni)
                    MMA_TF32(acc[mi][ni], fa[0][mi], fb[0][ni]);

            if (s + 1 < nst) {
                cp_wait<1>();
                __syncthreads();
                const float* asn = AsBase + ((s + 1) & (STAGES - 1)) * AS_ELEMS;
                const float* bsn = BsBase + ((s + 1) & (STAGES - 1)) * BS_ELEMS;
                load_frag_a(fa[0], asn, wm, g, tg, 0);
                load_frag_b(fb[0], bsn, wn, g, tg, 0);
            }
            #pragma unroll
            for (int mi = 0; mi < 4; ++mi)
                #pragma unroll
                for (int ni = 0; ni < 4; ++ni)
                    MMA_TF32(acc[mi][ni], fa[1][mi], fb[1][ni]);
        }

        // epilogue (registers + global only)
        #pragma unroll
        for (int mi = 0; mi < 4; ++mi) {
            int r0 = bm + wm + mi * 16 + g;
            int r1 = r0 + 8;
            #pragma unroll
            for (int ni = 0; ni < 4; ++ni) {
                int col = bn + wn + ni * 8 + 2 * tg;
                float2 bb = *(const float2*)&bias[col];
                #pragma unroll
                for (int half_ = 0; half_ < 2; ++half_) {
                    int row = half_ ? r1 : r0;
                    if (row >= M) continue;
                    float vx = acc[mi][ni][half_ * 2 + 0] + bb.x;
                    float vy = acc[mi][ni][half_ * 2 + 1] + bb.y;
                    if (res) {
                        float2 rr = *(const float2*)&res[(size_t)row * N + col];
                        vx += rr.x; vy += rr.y;
                    }
                    if (RELU) { vx = fmaxf(vx, 0.f); vy = fmaxf(vy, 0.f); }
                    if constexpr (sizeof(OutT) == 2) {
                        *(__half2*)&C[(size_t)row * N + col] = __floats2half2_rn(vx, vy);
                    } else {
                        *(float2*)&C[(size_t)row * N + col] = make_float2(vx, vy);
                    }
                }
            }
        }

        // drain outstanding (possibly empty) groups; make smem safe for the
        // next tile's prologue against slow warps still reading this tile
        cp_wait<0>();
        __syncthreads();
    }
}

// ---------------------------------------------------------------------------
// Deformable sampling, fused softmax, 2 heads per warp (unchanged from R7)
// ---------------------------------------------------------------------------
__global__ void sample_kernel(const __half* __restrict__ value,
                              const float* __restrict__ off,
                              const float* __restrict__ logits,
                              const float* __restrict__ ref,
                              float* __restrict__ out) {
    int gtid = blockIdx.x * blockDim.x + threadIdx.x;
    int gw = gtid >> 5;
    int lane = gtid & 31;
    if (gw >= TOK * 4) return;
    int q = gw >> 2;
    int hp = gw & 3;
    int h = hp * 2 + (lane >> 4);
    int sub = lane & 15;
    int b = q / LEN;

    const int HS[4] = {100, 50, 25, 13};
    const int ST[4] = {0, 10000, 12500, 13125};

    float lg = logits[(size_t)q * 128 + h * 16 + sub];
    float m = lg;
    #pragma unroll
    for (int o = 8; o > 0; o >>= 1) m = fmaxf(m, __shfl_xor_sync(0xffffffffu, m, o));
    float e = __expf(lg - m);
    float ssum = e;
    #pragma unroll
    for (int o = 8; o > 0; o >>= 1) ssum += __shfl_xor_sync(0xffffffffu, ssum, o);
    float wnorm = e / ssum;

    const float* offp = off + (size_t)q * 256 + h * 32;
    const float* refp = ref + (size_t)q * 8;
    const __half2* vb = (const __half2*)(value + (size_t)b * LEN * 256 + h * 32) + sub;

    float accx = 0.f, accy = 0.f;
    #pragma unroll
    for (int l = 0; l < 4; ++l) {
        const int Hl = HS[l];
        const int st = ST[l];
        float rx = refp[l * 2 + 0];
        float ry = refp[l * 2 + 1];
        #pragma unroll
        for (int p = 0; p < 4; ++p) {
            int idx = l * 4 + p;
            float ox = offp[idx * 2 + 0];
            float oy = offp[idx * 2 + 1];
            float w  = __shfl_sync(0xffffffffu, wnorm, (lane & 16) | idx);
            float x = fmaf(rx, (float)Hl, ox - 0.5f);
            float y = fmaf(ry, (float)Hl, oy - 0.5f);
            float x0f = floorf(x), y0f = floorf(y);
            int x0 = (int)x0f, y0 = (int)y0f;
            float dx = x - x0f, dy = y - y0f;

            float mx0 = (x0 >= 0 && x0 < Hl) ? 1.f : 0.f;
            float mx1 = (x0 + 1 >= 0 && x0 + 1 < Hl) ? 1.f : 0.f;
            float my0 = (y0 >= 0 && y0 < Hl) ? 1.f : 0.f;
            float my1 = (y0 + 1 >= 0 && y0 + 1 < Hl) ? 1.f : 0.f;

            int x0c = min(max(x0, 0), Hl - 1);
            int x1c = min(max(x0 + 1, 0), Hl - 1);
            int y0c = min(max(y0, 0), Hl - 1);
            int y1c = min(max(y0 + 1, 0), Hl - 1);

            float w00 = (1.f - dx) * (1.f - dy) * mx0 * my0 * w;
            float w10 = dx * (1.f - dy) * mx1 * my0 * w;
            float w01 = (1.f - dx) * dy * mx0 * my1 * w;
            float w11 = dx * dy * mx1 * my1 * w;

            int r0 = st + y0c * Hl;
            int r1 = st + y1c * Hl;
            float2 v00 = __half22float2(vb[(size_t)(r0 + x0c) * 128]);
            float2 v10 = __half22float2(vb[(size_t)(r0 + x1c) * 128]);
            float2 v01 = __half22float2(vb[(size_t)(r1 + x0c) * 128]);
            float2 v11 = __half22float2(vb[(size_t)(r1 + x1c) * 128]);

            accx += w00 * v00.x + w10 * v10.x + w01 * v01.x + w11 * v11.x;
            accy += w00 * v00.y + w10 * v10.y + w01 * v01.y + w11 * v11.y;
        }
    }
    *(float2*)&out[(size_t)q * 256 + h * 32 + 2 * sub] = make_float2(accx, accy);
}

// ---------------------------------------------------------------------------
// LayerNorm over D=256: one warp per row (unchanged from R7)
// ---------------------------------------------------------------------------
__global__ void ln_kernel(const float* __restrict__ x, const float* __restrict__ g,
                          const float* __restrict__ be, float* __restrict__ y,
                          int nrows) {
    int gtid = blockIdx.x * blockDim.x + threadIdx.x;
    int row = gtid >> 5;
    int lane = gtid & 31;
    if (row >= nrows) return;
    const float* p = x + (size_t)row * 256 + lane * 8;
    float v[8];
    *(float4*)&v[0] = *(const float4*)(p + 0);
    *(float4*)&v[4] = *(const float4*)(p + 4);
    float s = 0.f;
    #pragma unroll
    for (int i = 0; i < 8; ++i) s += v[i];
    #pragma unroll
    for (int o = 16; o > 0; o >>= 1) s += __shfl_xor_sync(0xffffffffu, s, o);
    float mean = s * (1.f / 256.f);
    float vs = 0.f;
    #pragma unroll
    for (int i = 0; i < 8; ++i) { float d = v[i] - mean; vs += d * d; }
    #pragma unroll
    for (int o = 16; o > 0; o >>= 1) vs += __shfl_xor_sync(0xffffffffu, vs, o);
    float rstd = rsqrtf(vs * (1.f / 256.f) + LN_EPS);
    float* q = y + (size_t)row * 256 + lane * 8;
    const float* gp = g + lane * 8;
    const float* bp = be + lane * 8;
    float go[8], bo[8];
    *(float4*)&go[0] = *(const float4*)(gp + 0);
    *(float4*)&go[4] = *(const float4*)(gp + 4);
    *(float4*)&bo[0] = *(const float4*)(bp + 0);
    *(float4*)&bo[4] = *(const float4*)(bp + 4);
    #pragma unroll
    for (int i = 0; i < 8; ++i) v[i] = (v[i] - mean) * rstd * go[i] + bo[i];
    *(float4*)(q + 0) = *(float4*)&v[0];
    *(float4*)(q + 4) = *(float4*)&v[4];
}

// ---------------------------------------------------------------------------
// Host launch
// ---------------------------------------------------------------------------
extern "C" void kernel_launch(void* const* d_in, const int* in_sizes, int n_in,
                              void* d_out, int out_size) {
    const float* src     = (const float*)d_in[0];
    const float* pos     = (const float*)d_in[1];
    const float* refpts  = (const float*)d_in[2];
    const float* W_value = (const float*)d_in[3];
    const float* b_value = (const float*)d_in[4];
    const float* W_off   = (const float*)d_in[5];
    const float* b_off   = (const float*)d_in[6];
    const float* W_attn  = (const float*)d_in[7];
    const float* b_attn  = (const float*)d_in[8];
    const float* W_out   = (const float*)d_in[9];
    const float* b_out   = (const float*)d_in[10];
    const float* W1      = (const float*)d_in[11];
    const float* b1      = (const float*)d_in[12];
    const float* W2      = (const float*)d_in[13];
    const float* b2      = (const float*)d_in[14];
    const float* g1      = (const float*)d_in[15];
    const float* be1     = (const float*)d_in[16];
    const float* g2      = (const float*)d_in[17];
    const float* be2     = (const float*)d_in[18];
    float* out = (float*)d_out;

    void* sp = nullptr;
    cudaGetSymbolAddress(&sp, g_scratch);
    float* base      = (float*)sp;
    float* g_query   = base;
    float* g_valuef  = g_query   + SZ256;
    float* g_off     = g_valuef  + SZ256;
    float* g_attnout = g_off     + SZ256;
    float* g_x1      = g_attnout + SZ256;
    float* g_ln1     = g_x1      + SZ256;
    float* g_x2      = g_ln1     + SZ256;
    float* g_attw    = g_x2      + SZ256;
    float* g_hid     = g_attw    + SZ128;
    __half* g_value_h = (__half*)g_valuef;

    cudaFuncSetAttribute(gemm_tc<false, float>,
                         cudaFuncAttributeMaxDynamicSharedMemorySize, GEMM_SMEM_BYTES);
    cudaFuncSetAttribute(gemm_tc<true, float>,
                         cudaFuncAttributeMaxDynamicSharedMemorySize, GEMM_SMEM_BYTES);
    cudaFuncSetAttribute(gemm_tc<false, __half>,
                         cudaFuncAttributeMaxDynamicSharedMemorySize, GEMM_SMEM_BYTES);

    const int M = TOK;
    const int gy = (M + 127) / 128;   // 208

    auto launch_gemm = [&](auto relu_tag, auto* Cptr, const float* Aptr,
                           const float* Wptr, const float* bptr,
                           const float* rptr, int N, int K) {
        constexpr bool RELU = decltype(relu_tag)::value;
        const int nbx = N / 128;
        const int ntiles = nbx * gy;
        const int grid = ntiles < NPERSIST ? ntiles : NPERSIST;
        gemm_tc<RELU><<<grid, 256, GEMM_SMEM_BYTES>>>(
            Aptr, Wptr, bptr, rptr, Cptr, M, N, K, nbx, ntiles);
    };

    // 1) query = src + pos
    {
        int n4 = (int)(SZ256 / 4);
        add_kernel<<<(n4 + 255) / 256, 256>>>(src, pos, g_query, n4);
    }
    // 2) value = src @ Wv + bv  -> fp16
    launch_gemm(std::integral_constant<bool, false>{}, g_value_h, src, W_value, b_value, (const float*)nullptr, 256, 256);
    // 3) off = query @ Woff + boff
    launch_gemm(std::integral_constant<bool, false>{}, g_off, g_query, W_off, b_off, (const float*)nullptr, 256, 256);
    // 4) attw logits
    launch_gemm(std::integral_constant<bool, false>{}, g_attw, g_query, W_attn, b_attn, (const float*)nullptr, 128, 256);
    // 5) sampling (+softmax)
    {
        int nthreads = TOK * 4 * 32;
        sample_kernel<<<(nthreads + 255) / 256, 256>>>(g_value_h, g_off, g_attw, refpts, g_attnout);
    }
    // 6) x1 = attnout @ Wout + bout + src
    launch_gemm(std::integral_constant<bool, false>{}, g_x1, g_attnout, W_out, b_out, src, 256, 256);
    // 7) ln1
    {
        int nthreads = TOK * 32;
        ln_kernel<<<(nthreads + 255) / 256, 256>>>(g_x1, g1, be1, g_ln1, TOK);
    }
    // 8) hid = relu(ln1 @ W1 + b1)
    launch_gemm(std::integral_constant<bool, true>{}, g_hid, g_ln1, W1, b1, (const float*)nullptr, 1024, 256);
    // 9) x2 = hid @ W2 + b2 + ln1
    launch_gemm(std::integral_constant<bool, false>{}, g_x2, g_hid, W2, b2, g_ln1, 256, 1024);
    // 10) out = LN(x2)
    {
        int nthreads = TOK * 32;
        ln_kernel<<<(nthreads + 255) / 256, 256>>>(g_x2, g2, be2, out, TOK);
    }
}

// round 13
// speedup vs baseline: 1.3110x; 1.3110x over previous
#include <cuda_runtime.h>
#include <cuda_fp16.h>
#include <cuda_bf16.h>
#include <cstdint>
#include <cstddef>

// ---------------------------------------------------------------------------
// Problem constants
// ---------------------------------------------------------------------------
#define LEN   13294          // 100*100 + 50*50 + 25*25 + 13*13
#define BATCH 2
#define TOK   (BATCH * LEN)  // 26588
#define NHEAD  8
#define LN_EPS 1e-5f

#define SZ256  ((size_t)TOK * 256)
#define SZ128  ((size_t)TOK * 128)
#define SZ1024 ((size_t)TOK * 1024)

__device__ float g_scratch[7 * SZ256 + SZ128 + SZ1024];

// ---------------------------------------------------------------------------
// Elementwise add
// ---------------------------------------------------------------------------
__global__ void add_kernel(const float* __restrict__ a, const float* __restrict__ b,
                           float* __restrict__ c, int n4) {
    int i = blockIdx.x * blockDim.x + threadIdx.x;
    if (i >= n4) return;
    float4 va = ((const float4*)a)[i];
    float4 vb = ((const float4*)b)[i];
    ((float4*)c)[i] = make_float4(va.x + vb.x, va.y + vb.y, va.z + vb.z, va.w + vb.w);
}

// ---------------------------------------------------------------------------
// cp.async helpers
// ---------------------------------------------------------------------------
__device__ __forceinline__ void cp_async16(void* smem, const void* gmem, bool pred) {
    uint32_t s = (uint32_t)__cvta_generic_to_shared(smem);
    int sz = pred ? 16 : 0;
    asm volatile("cp.async.cg.shared.global [%0], [%1], 16, %2;\n"
                 :: "r"(s), "l"(gmem), "r"(sz));
}
__device__ __forceinline__ void cp_commit() {
    asm volatile("cp.async.commit_group;\n" ::);
}
template <int N>
__device__ __forceinline__ void cp_wait() {
    asm volatile("cp.async.wait_group %0;\n" :: "n"(N));
}

#define MMA_TF32(d, a, b)                                                     \
    asm volatile(                                                             \
        "mma.sync.aligned.m16n8k8.row.col.f32.tf32.tf32.f32 "                 \
        "{%0,%1,%2,%3},{%4,%5,%6,%7},{%8,%9},{%0,%1,%2,%3};"                  \
        : "+f"(d[0]), "+f"(d[1]), "+f"(d[2]), "+f"(d[3])                      \
        : "r"(a[0]), "r"(a[1]), "r"(a[2]), "r"(a[3]), "r"(b[0]), "r"(b[1]))

// ---------------------------------------------------------------------------
// TF32 tensor-core GEMM — byte-identical to the R7 (580us) winner.
// 4-stage cp.async pipeline + fragment double-buffer.
// Block tile 128x128, BK=16, 256 threads (8 warps), warp tile 64x32.
// ---------------------------------------------------------------------------
#define AS_STRIDE 20    // 16 + 4 pad
#define BS_STRIDE 136   // 128 + 8 pad
#define STAGES 4
#define AS_ELEMS (128 * AS_STRIDE)
#define BS_ELEMS (16 * BS_STRIDE)
#define GEMM_SMEM_BYTES (STAGES * (AS_ELEMS + BS_ELEMS) * 4)   // 75,776

__device__ __forceinline__ void load_frag_a(uint32_t (&a)[4][4], const float* asb,
                                            int wm, int g, int tg, int kk) {
    #pragma unroll
    for (int mi = 0; mi < 4; ++mi) {
        int base = (wm + mi * 16 + g) * AS_STRIDE + kk + tg;
        a[mi][0] = __float_as_uint(asb[base]);
        a[mi][1] = __float_as_uint(asb[base + 8 * AS_STRIDE]);
        a[mi][2] = __float_as_uint(asb[base + 4]);
        a[mi][3] = __float_as_uint(asb[base + 8 * AS_STRIDE + 4]);
    }
}
__device__ __forceinline__ void load_frag_b(uint32_t (&b)[4][2], const float* bsb,
                                            int wn, int g, int tg, int kk) {
    #pragma unroll
    for (int ni = 0; ni < 4; ++ni) {
        int c = wn + ni * 8 + g;
        b[ni][0] = __float_as_uint(bsb[(kk + tg) * BS_STRIDE + c]);
        b[ni][1] = __float_as_uint(bsb[(kk + tg + 4) * BS_STRIDE + c]);
    }
}

template <bool RELU, typename OutT>
__global__ __launch_bounds__(256, 2) void gemm_tc(
    const float* __restrict__ A, const float* __restrict__ W,
    const float* __restrict__ bias, const float* __restrict__ res,
    OutT* __restrict__ C, int M, int N, int K)
{
    extern __shared__ float smem[];
    float* AsBase = smem;
    float* BsBase = smem + STAGES * AS_ELEMS;

    const int bm = blockIdx.y * 128;
    const int bn = blockIdx.x * 128;
    const int tid = threadIdx.x;
    const int wid = tid >> 5, lane = tid & 31;
    const int wm = (wid & 1) * 64;
    const int wn = (wid >> 1) * 32;
    const int g = lane >> 2, tg = lane & 3;

    const int arow = tid >> 1;            // 0..127
    const int acol = (tid & 1) * 8;       // 0 or 8
    const int brow = tid >> 4;            // 0..15
    const int bcol = (tid & 15) * 8;      // 0..120
    const bool aok = (bm + arow) < M;
    const float* Ap = A + (size_t)(bm + arow) * K + acol;
    const float* Bp = W + (size_t)brow * N + bn + bcol;

    const int nst = K >> 4;

    // prologue: issue stages 0..STAGES-2
    #pragma unroll
    for (int s = 0; s < STAGES - 1; ++s) {
        const int k0 = s << 4;
        float* as = AsBase + s * AS_ELEMS;
        float* bs = BsBase + s * BS_ELEMS;
        cp_async16(&as[arow * AS_STRIDE + acol],     Ap + k0,     aok);
        cp_async16(&as[arow * AS_STRIDE + acol + 4], Ap + k0 + 4, aok);
        const float* bp = Bp + (size_t)k0 * N;
        cp_async16(&bs[brow * BS_STRIDE + bcol],     bp,     true);
        cp_async16(&bs[brow * BS_STRIDE + bcol + 4], bp + 4, true);
        cp_commit();
    }

    float acc[4][4][4];
    #pragma unroll
    for (int mi = 0; mi < 4; ++mi)
        #pragma unroll
        for (int ni = 0; ni < 4; ++ni)
            #pragma unroll
            for (int e = 0; e < 4; ++e) acc[mi][ni][e] = 0.f;

    uint32_t fa[2][4][4], fb[2][4][2];

    cp_wait<1>();
    __syncthreads();
    load_frag_a(fa[0], AsBase, wm, g, tg, 0);
    load_frag_b(fb[0], BsBase, wn, g, tg, 0);

    for (int s = 0; s < nst; ++s) {
        {
            const int sn = s + STAGES - 1;
            if (sn < nst) {
                const int buf = sn & (STAGES - 1);
                const int k0 = sn << 4;
                float* as = AsBase + buf * AS_ELEMS;
                float* bs = BsBase + buf * BS_ELEMS;
                cp_async16(&as[arow * AS_STRIDE + acol],     Ap + k0,     aok);
                cp_async16(&as[arow * AS_STRIDE + acol + 4], Ap + k0 + 4, aok);
                const float* bp = Bp + (size_t)k0 * N;
                cp_async16(&bs[brow * BS_STRIDE + bcol],     bp,     true);
                cp_async16(&bs[brow * BS_STRIDE + bcol + 4], bp + 4, true);
            }
            cp_commit();
        }

        const float* asb = AsBase + (s & (STAGES - 1)) * AS_ELEMS;
        const float* bsb = BsBase + (s & (STAGES - 1)) * BS_ELEMS;

        load_frag_a(fa[1], asb, wm, g, tg, 8);
        load_frag_b(fb[1], bsb, wn, g, tg, 8);
        #pragma unroll
        for (int mi = 0; mi < 4; ++mi)
            #pragma unroll
            for (int ni = 0; ni < 4; ++ni)
                MMA_TF32(acc[mi][ni], fa[0][mi], fb[0][ni]);

        if (s + 1 < nst) {
            cp_wait<1>();
            __syncthreads();
            const float* asn = AsBase + ((s + 1) & (STAGES - 1)) * AS_ELEMS;
            const float* bsn = BsBase + ((s + 1) & (STAGES - 1)) * BS_ELEMS;
            load_frag_a(fa[0], asn, wm, g, tg, 0);
            load_frag_b(fb[0], bsn, wn, g, tg, 0);
        }
        #pragma unroll
        for (int mi = 0; mi < 4; ++mi)
            #pragma unroll
            for (int ni = 0; ni < 4; ++ni)
                MMA_TF32(acc[mi][ni], fa[1][mi], fb[1][ni]);
    }

    // epilogue
    #pragma unroll
    for (int mi = 0; mi < 4; ++mi) {
        int r0 = bm + wm + mi * 16 + g;
        int r1 = r0 + 8;
        #pragma unroll
        for (int ni = 0; ni < 4; ++ni) {
            int col = bn + wn + ni * 8 + 2 * tg;
            float2 bb = *(const float2*)&bias[col];
            #pragma unroll
            for (int half_ = 0; half_ < 2; ++half_) {
                int row = half_ ? r1 : r0;
                if (row >= M) continue;
                float vx = acc[mi][ni][half_ * 2 + 0] + bb.x;
                float vy = acc[mi][ni][half_ * 2 + 1] + bb.y;
                if (res) {
                    float2 rr = *(const float2*)&res[(size_t)row * N + col];
                    vx += rr.x; vy += rr.y;
                }
                if (RELU) { vx = fmaxf(vx, 0.f); vy = fmaxf(vy, 0.f); }
                if constexpr (sizeof(OutT) == 2) {
                    *(__half2*)&C[(size_t)row * N + col] = __floats2half2_rn(vx, vy);
                } else {
                    *(float2*)&C[(size_t)row * N + col] = make_float2(vx, vy);
                }
            }
        }
    }
}

// ---------------------------------------------------------------------------
// Deformable sampling v2: parallel per-lane precompute + shfl-broadcast.
// One warp = 2 heads of one token (lanes 0..15 head h0, 16..31 head h1).
// Phase 1 (parallel): lane `sub` computes sample sub's 4 flat gather indices
//   and 4 weights (bilinear x in-bounds x softmax) for its half-warp's head.
// Phase 2 (serial over 16 samples): shfl-broadcast 8 values, 4 half2 loads,
//   8 FMA. value fp16 [tok,256].
// ---------------------------------------------------------------------------
__global__ void sample_kernel(const __half* __restrict__ value,
                              const float* __restrict__ off,
                              const float* __restrict__ logits,
                              const float* __restrict__ ref,
                              float* __restrict__ out) {
    int gtid = blockIdx.x * blockDim.x + threadIdx.x;
    int gw = gtid >> 5;
    int lane = gtid & 31;
    if (gw >= TOK * 4) return;
    int q = gw >> 2;
    int hp = gw & 3;
    int h = hp * 2 + (lane >> 4);   // this half-warp's head
    int sub = lane & 15;            // sample index owned by this lane
    int b = q / LEN;

    const int HS[4] = {100, 50, 25, 13};
    const int ST[4] = {0, 10000, 12500, 13125};

    // softmax over this head's 16 logits (lane sub <-> logit sub)
    float lg = logits[(size_t)q * 128 + h * 16 + sub];
    float m = lg;
    #pragma unroll
    for (int o = 8; o > 0; o >>= 1) m = fmaxf(m, __shfl_xor_sync(0xffffffffu, m, o));
    float e = __expf(lg - m);
    float ssum = e;
    #pragma unroll
    for (int o = 8; o > 0; o >>= 1) ssum += __shfl_xor_sync(0xffffffffu, ssum, o);
    float wnorm = e / ssum;         // own sample's softmax weight

    // ---- phase 1: per-lane precompute of own sample ----
    const int l = sub >> 2;         // level of sample sub
    const int Hl = HS[l];
    const int st = ST[l];
    const float* refp = ref + (size_t)q * 8;
    float rx = refp[l * 2 + 0];
    float ry = refp[l * 2 + 1];
    float2 od = *(const float2*)(off + (size_t)q * 256 + h * 32 + 2 * sub);

    float x = fmaf(rx, (float)Hl, od.x - 0.5f);
    float y = fmaf(ry, (float)Hl, od.y - 0.5f);
    float x0f = floorf(x), y0f = floorf(y);
    int x0 = (int)x0f, y0 = (int)y0f;
    float dx = x - x0f, dy = y - y0f;

    float mx0 = (x0 >= 0 && x0 < Hl) ? 1.f : 0.f;
    float mx1 = (x0 + 1 >= 0 && x0 + 1 < Hl) ? 1.f : 0.f;
    float my0 = (y0 >= 0 && y0 < Hl) ? 1.f : 0.f;
    float my1 = (y0 + 1 >= 0 && y0 + 1 < Hl) ? 1.f : 0.f;

    int x0c = min(max(x0, 0), Hl - 1);
    int x1c = min(max(x0 + 1, 0), Hl - 1);
    int y0c = min(max(y0, 0), Hl - 1);
    int y1c = min(max(y0 + 1, 0), Hl - 1);

    // weights premultiplied by softmax weight
    float wv00 = (1.f - dx) * (1.f - dy) * mx0 * my0 * wnorm;
    float wv10 = dx * (1.f - dy) * mx1 * my0 * wnorm;
    float wv01 = (1.f - dx) * dy * mx0 * my1 * wnorm;
    float wv11 = dx * dy * mx1 * my1 * wnorm;

    int r0 = st + y0c * Hl;
    int r1 = st + y1c * Hl;
    int i00 = r0 + x0c;
    int i10 = r0 + x1c;
    int i01 = r1 + x0c;
    int i11 = r1 + x1c;

    // ---- phase 2: gather loop (4 loads + 8 shfl + 8 fma per sample) ----
    // vb: this lane's channel pair within (b, h); token stride = 128 half2
    const __half2* vb = (const __half2*)(value + (size_t)b * LEN * 256 + h * 32) + sub;
    const int hbit = lane & 16;

    float accx = 0.f, accy = 0.f;
    #pragma unroll
    for (int s = 0; s < 16; ++s) {
        int srcl = hbit | s;
        int p00 = __shfl_sync(0xffffffffu, i00, srcl);
        int p10 = __shfl_sync(0xffffffffu, i10, srcl);
        int p01 = __shfl_sync(0xffffffffu, i01, srcl);
        int p11 = __shfl_sync(0xffffffffu, i11, srcl);
        float u00 = __shfl_sync(0xffffffffu, wv00, srcl);
        float u10 = __shfl_sync(0xffffffffu, wv10, srcl);
        float u01 = __shfl_sync(0xffffffffu, wv01, srcl);
        float u11 = __shfl_sync(0xffffffffu, wv11, srcl);

        float2 v00 = __half22float2(vb[(size_t)p00 * 128]);
        float2 v10 = __half22float2(vb[(size_t)p10 * 128]);
        float2 v01 = __half22float2(vb[(size_t)p01 * 128]);
        float2 v11 = __half22float2(vb[(size_t)p11 * 128]);

        accx = fmaf(u00, v00.x, accx);
        accy = fmaf(u00, v00.y, accy);
        accx = fmaf(u10, v10.x, accx);
        accy = fmaf(u10, v10.y, accy);
        accx = fmaf(u01, v01.x, accx);
        accy = fmaf(u01, v01.y, accy);
        accx = fmaf(u11, v11.x, accx);
        accy = fmaf(u11, v11.y, accy);
    }
    *(float2*)&out[(size_t)q * 256 + h * 32 + 2 * sub] = make_float2(accx, accy);
}

// ---------------------------------------------------------------------------
// LayerNorm over D=256: one warp per row (unchanged)
// ---------------------------------------------------------------------------
__global__ void ln_kernel(const float* __restrict__ x, const float* __restrict__ g,
                          const float* __restrict__ be, float* __restrict__ y,
                          int nrows) {
    int gtid = blockIdx.x * blockDim.x + threadIdx.x;
    int row = gtid >> 5;
    int lane = gtid & 31;
    if (row >= nrows) return;
    const float* p = x + (size_t)row * 256 + lane * 8;
    float v[8];
    *(float4*)&v[0] = *(const float4*)(p + 0);
    *(float4*)&v[4] = *(const float4*)(p + 4);
    float s = 0.f;
    #pragma unroll
    for (int i = 0; i < 8; ++i) s += v[i];
    #pragma unroll
    for (int o = 16; o > 0; o >>= 1) s += __shfl_xor_sync(0xffffffffu, s, o);
    float mean = s * (1.f / 256.f);
    float vs = 0.f;
    #pragma unroll
    for (int i = 0; i < 8; ++i) { float d = v[i] - mean; vs += d * d; }
    #pragma unroll
    for (int o = 16; o > 0; o >>= 1) vs += __shfl_xor_sync(0xffffffffu, vs, o);
    float rstd = rsqrtf(vs * (1.f / 256.f) + LN_EPS);
    float* q = y + (size_t)row * 256 + lane * 8;
    const float* gp = g + lane * 8;
    const float* bp = be + lane * 8;
    float go[8], bo[8];
    *(float4*)&go[0] = *(const float4*)(gp + 0);
    *(float4*)&go[4] = *(const float4*)(gp + 4);
    *(float4*)&bo[0] = *(const float4*)(bp + 0);
    *(float4*)&bo[4] = *(const float4*)(bp + 4);
    #pragma unroll
    for (int i = 0; i < 8; ++i) v[i] = (v[i] - mean) * rstd * go[i] + bo[i];
    *(float4*)(q + 0) = *(float4*)&v[0];
    *(float4*)(q + 4) = *(float4*)&v[4];
}

// ---------------------------------------------------------------------------
// Host launch
// ---------------------------------------------------------------------------
extern "C" void kernel_launch(void* const* d_in, const int* in_sizes, int n_in,
                              void* d_out, int out_size) {
    const float* src     = (const float*)d_in[0];
    const float* pos     = (const float*)d_in[1];
    const float* refpts  = (const float*)d_in[2];
    const float* W_value = (const float*)d_in[3];
    const float* b_value = (const float*)d_in[4];
    const float* W_off   = (const float*)d_in[5];
    const float* b_off   = (const float*)d_in[6];
    const float* W_attn  = (const float*)d_in[7];
    const float* b_attn  = (const float*)d_in[8];
    const float* W_out   = (const float*)d_in[9];
    const float* b_out   = (const float*)d_in[10];
    const float* W1      = (const float*)d_in[11];
    const float* b1      = (const float*)d_in[12];
    const float* W2      = (const float*)d_in[13];
    const float* b2      = (const float*)d_in[14];
    const float* g1      = (const float*)d_in[15];
    const float* be1     = (const float*)d_in[16];
    const float* g2      = (const float*)d_in[17];
    const float* be2     = (const float*)d_in[18];
    float* out = (float*)d_out;

    void* sp = nullptr;
    cudaGetSymbolAddress(&sp, g_scratch);
    float* base      = (float*)sp;
    float* g_query   = base;
    float* g_valuef  = g_query   + SZ256;
    float* g_off     = g_valuef  + SZ256;
    float* g_attnout = g_off     + SZ256;
    float* g_x1      = g_attnout + SZ256;
    float* g_ln1     = g_x1      + SZ256;
    float* g_x2      = g_ln1     + SZ256;
    float* g_attw    = g_x2      + SZ256;
    float* g_hid     = g_attw    + SZ128;
    __half* g_value_h = (__half*)g_valuef;

    cudaFuncSetAttribute(gemm_tc<false, float>,
                         cudaFuncAttributeMaxDynamicSharedMemorySize, GEMM_SMEM_BYTES);
    cudaFuncSetAttribute(gemm_tc<true, float>,
                         cudaFuncAttributeMaxDynamicSharedMemorySize, GEMM_SMEM_BYTES);
    cudaFuncSetAttribute(gemm_tc<false, __half>,
                         cudaFuncAttributeMaxDynamicSharedMemorySize, GEMM_SMEM_BYTES);

    const int M = TOK;
    const int gy = (M + 127) / 128;   // 208

    // 1+2) query = src + pos (two half-launches so the sampler is launch #6
    //      and gets captured by ncu's -s 5 -c 1)
    {
        int n4 = (int)(SZ256 / 4);
        int n4a = n4 / 2;
        int n4b = n4 - n4a;
        add_kernel<<<(n4a + 255) / 256, 256>>>(src, pos, g_query, n4a);
        add_kernel<<<(n4b + 255) / 256, 256>>>(src + (size_t)n4a * 4,
                                               pos + (size_t)n4a * 4,
                                               g_query + (size_t)n4a * 4, n4b);
    }
    // 3) value = src @ Wv + bv  -> fp16
    gemm_tc<false, __half><<<dim3(2, gy), 256, GEMM_SMEM_BYTES>>>(src, W_value, b_value, nullptr, g_value_h, M, 256, 256);
    // 4) off = query @ Woff + boff
    gemm_tc<false, float><<<dim3(2, gy), 256, GEMM_SMEM_BYTES>>>(g_query, W_off, b_off, nullptr, g_off, M, 256, 256);
    // 5) attw logits
    gemm_tc<false, float><<<dim3(1, gy), 256, GEMM_SMEM_BYTES>>>(g_query, W_attn, b_attn, nullptr, g_attw, M, 128, 256);
    // 6) sampling (+softmax)  <-- profiled launch
    {
        int nthreads = TOK * 4 * 32;
        sample_kernel<<<(nthreads + 255) / 256, 256>>>(g_value_h, g_off, g_attw, refpts, g_attnout);
    }
    // 7) x1 = attnout @ Wout + bout + src
    gemm_tc<false, float><<<dim3(2, gy), 256, GEMM_SMEM_BYTES>>>(g_attnout, W_out, b_out, src, g_x1, M, 256, 256);
    // 8) ln1
    {
        int nthreads = TOK * 32;
        ln_kernel<<<(nthreads + 255) / 256, 256>>>(g_x1, g1, be1, g_ln1, TOK);
    }
    // 9) hid = relu(ln1 @ W1 + b1)
    gemm_tc<true, float><<<dim3(8, gy), 256, GEMM_SMEM_BYTES>>>(g_ln1, W1, b1, nullptr, g_hid, M, 1024, 256);
    // 10) x2 = hid @ W2 + b2 + ln1
    gemm_tc<false, float><<<dim3(2, gy), 256, GEMM_SMEM_BYTES>>>(g_hid, W2, b2, g_ln1, g_x2, M, 256, 1024);
    // 11) out = LN(x2)
    {
        int nthreads = TOK * 32;
        ln_kernel<<<(nthreads + 255) / 256, 256>>>(g_x2, g2, be2, out, TOK);
    }
}

// round 15
// speedup vs baseline: 1.3230x; 1.0091x over previous
#include <cuda_runtime.h>
#include <cuda_fp16.h>
#include <cuda_bf16.h>
#include <cstdint>
#include <cstddef>

// ---------------------------------------------------------------------------
// Problem constants
// ---------------------------------------------------------------------------
#define LEN   13294          // 100*100 + 50*50 + 25*25 + 13*13
#define BATCH 2
#define TOK   (BATCH * LEN)  // 26588
#define NHEAD  8
#define LN_EPS 1e-5f

#define SZ256  ((size_t)TOK * 256)
#define SZ128  ((size_t)TOK * 128)
#define SZ384  ((size_t)TOK * 384)
#define SZ1024 ((size_t)TOK * 1024)

// query, value(h), oa (384), attnout, x1, ln1, x2, hid + concat weights
#define SCRATCH_FLOATS (6 * SZ256 + SZ384 + SZ1024 + 256 * 384 + 384 + 1024)
__device__ float g_scratch[SCRATCH_FLOATS];

// ---------------------------------------------------------------------------
// Elementwise add
// ---------------------------------------------------------------------------
__global__ void add_kernel(const float* __restrict__ a, const float* __restrict__ b,
                           float* __restrict__ c, int n4) {
    int i = blockIdx.x * blockDim.x + threadIdx.x;
    if (i >= n4) return;
    float4 va = ((const float4*)a)[i];
    float4 vb = ((const float4*)b)[i];
    ((float4*)c)[i] = make_float4(va.x + vb.x, va.y + vb.y, va.z + vb.z, va.w + vb.w);
}

// ---------------------------------------------------------------------------
// Concat W_off [256,256] and W_attn [256,128] -> Wcat [256,384]; biases too.
// ---------------------------------------------------------------------------
__global__ void concat_kernel(const float* __restrict__ Woff, const float* __restrict__ Wattn,
                              const float* __restrict__ boff, const float* __restrict__ battn,
                              float* __restrict__ Wcat, float* __restrict__ bcat) {
    int i = blockIdx.x * blockDim.x + threadIdx.x;
    int total = 256 * 384;
    if (i < total) {
        int k = i / 384, n = i % 384;
        Wcat[i] = (n < 256) ? Woff[k * 256 + n] : Wattn[k * 128 + (n - 256)];
    }
    if (i < 384) {
        bcat[i] = (i < 256) ? boff[i] : battn[i - 256];
    }
}

// ---------------------------------------------------------------------------
// cp.async helpers
// ---------------------------------------------------------------------------
__device__ __forceinline__ void cp_async16(void* smem, const void* gmem, bool pred) {
    uint32_t s = (uint32_t)__cvta_generic_to_shared(smem);
    int sz = pred ? 16 : 0;
    asm volatile("cp.async.cg.shared.global [%0], [%1], 16, %2;\n"
                 :: "r"(s), "l"(gmem), "r"(sz));
}
__device__ __forceinline__ void cp_commit() {
    asm volatile("cp.async.commit_group;\n" ::);
}
template <int N>
__device__ __forceinline__ void cp_wait() {
    asm volatile("cp.async.wait_group %0;\n" :: "n"(N));
}

#define MMA_TF32(d, a, b)                                                     \
    asm volatile(                                                             \
        "mma.sync.aligned.m16n8k8.row.col.f32.tf32.tf32.f32 "                 \
        "{%0,%1,%2,%3},{%4,%5,%6,%7},{%8,%9},{%0,%1,%2,%3};"                  \
        : "+f"(d[0]), "+f"(d[1]), "+f"(d[2]), "+f"(d[3])                      \
        : "r"(a[0]), "r"(a[1]), "r"(a[2]), "r"(a[3]), "r"(b[0]), "r"(b[1]))

// ---------------------------------------------------------------------------
// TF32 tensor-core GEMM — byte-identical core to the R7/R13 winner.
// 4-stage cp.async pipeline + fragment double-buffer.
// Block tile 128x128, BK=16, 256 threads (8 warps), warp tile 64x32.
// ---------------------------------------------------------------------------
#define AS_STRIDE 20    // 16 + 4 pad
#define BS_STRIDE 136   // 128 + 8 pad
#define STAGES 4
#define AS_ELEMS (128 * AS_STRIDE)
#define BS_ELEMS (16 * BS_STRIDE)
#define GEMM_SMEM_BYTES (STAGES * (AS_ELEMS + BS_ELEMS) * 4)   // 75,776

__device__ __forceinline__ void load_frag_a(uint32_t (&a)[4][4], const float* asb,
                                            int wm, int g, int tg, int kk) {
    #pragma unroll
    for (int mi = 0; mi < 4; ++mi) {
        int base = (wm + mi * 16 + g) * AS_STRIDE + kk + tg;
        a[mi][0] = __float_as_uint(asb[base]);
        a[mi][1] = __float_as_uint(asb[base + 8 * AS_STRIDE]);
        a[mi][2] = __float_as_uint(asb[base + 4]);
        a[mi][3] = __float_as_uint(asb[base + 8 * AS_STRIDE + 4]);
    }
}
__device__ __forceinline__ void load_frag_b(uint32_t (&b)[4][2], const float* bsb,
                                            int wn, int g, int tg, int kk) {
    #pragma unroll
    for (int ni = 0; ni < 4; ++ni) {
        int c = wn + ni * 8 + g;
        b[ni][0] = __float_as_uint(bsb[(kk + tg) * BS_STRIDE + c]);
        b[ni][1] = __float_as_uint(bsb[(kk + tg + 4) * BS_STRIDE + c]);
    }
}

template <bool RELU, typename OutT>
__global__ __launch_bounds__(256, 2) void gemm_tc(
    const float* __restrict__ A, const float* __restrict__ W,
    const float* __restrict__ bias, const float* __restrict__ res,
    OutT* __restrict__ C, int M, int N, int K)
{
    extern __shared__ float smem[];
    float* AsBase = smem;
    float* BsBase = smem + STAGES * AS_ELEMS;

    const int bm = blockIdx.y * 128;
    const int bn = blockIdx.x * 128;
    const int tid = threadIdx.x;
    const int wid = tid >> 5, lane = tid & 31;
    const int wm = (wid & 1) * 64;
    const int wn = (wid >> 1) * 32;
    const int g = lane >> 2, tg = lane & 3;

    const int arow = tid >> 1;            // 0..127
    const int acol = (tid & 1) * 8;       // 0 or 8
    const int brow = tid >> 4;            // 0..15
    const int bcol = (tid & 15) * 8;      // 0..120
    const bool aok = (bm + arow) < M;
    const float* Ap = A + (size_t)(bm + arow) * K + acol;
    const float* Bp = W + (size_t)brow * N + bn + bcol;

    const int nst = K >> 4;

    // prologue: issue stages 0..STAGES-2
    #pragma unroll
    for (int s = 0; s < STAGES - 1; ++s) {
        const int k0 = s << 4;
        float* as = AsBase + s * AS_ELEMS;
        float* bs = BsBase + s * BS_ELEMS;
        cp_async16(&as[arow * AS_STRIDE + acol],     Ap + k0,     aok);
        cp_async16(&as[arow * AS_STRIDE + acol + 4], Ap + k0 + 4, aok);
        const float* bp = Bp + (size_t)k0 * N;
        cp_async16(&bs[brow * BS_STRIDE + bcol],     bp,     true);
        cp_async16(&bs[brow * BS_STRIDE + bcol + 4], bp + 4, true);
        cp_commit();
    }

    float acc[4][4][4];
    #pragma unroll
    for (int mi = 0; mi < 4; ++mi)
        #pragma unroll
        for (int ni = 0; ni < 4; ++ni)
            #pragma unroll
            for (int e = 0; e < 4; ++e) acc[mi][ni][e] = 0.f;

    uint32_t fa[2][4][4], fb[2][4][2];

    cp_wait<1>();
    __syncthreads();
    load_frag_a(fa[0], AsBase, wm, g, tg, 0);
    load_frag_b(fb[0], BsBase, wn, g, tg, 0);

    for (int s = 0; s < nst; ++s) {
        {
            const int sn = s + STAGES - 1;
            if (sn < nst) {
                const int buf = sn & (STAGES - 1);
                const int k0 = sn << 4;
                float* as = AsBase + buf * AS_ELEMS;
                float* bs = BsBase + buf * BS_ELEMS;
                cp_async16(&as[arow * AS_STRIDE + acol],     Ap + k0,     aok);
                cp_async16(&as[arow * AS_STRIDE + acol + 4], Ap + k0 + 4, aok);
                const float* bp = Bp + (size_t)k0 * N;
                cp_async16(&bs[brow * BS_STRIDE + bcol],     bp,     true);
                cp_async16(&bs[brow * BS_STRIDE + bcol + 4], bp + 4, true);
            }
            cp_commit();
        }

        const float* asb = AsBase + (s & (STAGES - 1)) * AS_ELEMS;
        const float* bsb = BsBase + (s & (STAGES - 1)) * BS_ELEMS;

        load_frag_a(fa[1], asb, wm, g, tg, 8);
        load_frag_b(fb[1], bsb, wn, g, tg, 8);
        #pragma unroll
        for (int mi = 0; mi < 4; ++mi)
            #pragma unroll
            for (int ni = 0; ni < 4; ++ni)
                MMA_TF32(acc[mi][ni], fa[0][mi], fb[0][ni]);

        if (s + 1 < nst) {
            cp_wait<1>();
            __syncthreads();
            const float* asn = AsBase + ((s + 1) & (STAGES - 1)) * AS_ELEMS;
            const float* bsn = BsBase + ((s + 1) & (STAGES - 1)) * BS_ELEMS;
            load_frag_a(fa[0], asn, wm, g, tg, 0);
            load_frag_b(fb[0], bsn, wn, g, tg, 0);
        }
        #pragma unroll
        for (int mi = 0; mi < 4; ++mi)
            #pragma unroll
            for (int ni = 0; ni < 4; ++ni)
                MMA_TF32(acc[mi][ni], fa[1][mi], fb[1][ni]);
    }

    // epilogue
    #pragma unroll
    for (int mi = 0; mi < 4; ++mi) {
        int r0 = bm + wm + mi * 16 + g;
        int r1 = r0 + 8;
        #pragma unroll
        for (int ni = 0; ni < 4; ++ni) {
            int col = bn + wn + ni * 8 + 2 * tg;
            float2 bb = *(const float2*)&bias[col];
            #pragma unroll
            for (int half_ = 0; half_ < 2; ++half_) {
                int row = half_ ? r1 : r0;
                if (row >= M) continue;
                float vx = acc[mi][ni][half_ * 2 + 0] + bb.x;
                float vy = acc[mi][ni][half_ * 2 + 1] + bb.y;
                if (res) {
                    float2 rr = *(const float2*)&res[(size_t)row * N + col];
                    vx += rr.x; vy += rr.y;
                }
                if (RELU) { vx = fmaxf(vx, 0.f); vy = fmaxf(vy, 0.f); }
                if constexpr (sizeof(OutT) == 2) {
                    *(__half2*)&C[(size_t)row * N + col] = __floats2half2_rn(vx, vy);
                } else {
                    *(float2*)&C[(size_t)row * N + col] = make_float2(vx, vy);
                }
            }
        }
    }
}

// ---------------------------------------------------------------------------
// Deformable sampling v2 (parallel precompute + shfl-broadcast), reading the
// MERGED off/attw buffer: row stride 384; offsets at +0, logits at +256.
// ---------------------------------------------------------------------------
__global__ void sample_kernel(const __half* __restrict__ value,
                              const float* __restrict__ oa,   // [M, 384]
                              const float* __restrict__ ref,
                              float* __restrict__ out) {
    int gtid = blockIdx.x * blockDim.x + threadIdx.x;
    int gw = gtid >> 5;
    int lane = gtid & 31;
    if (gw >= TOK * 4) return;
    int q = gw >> 2;
    int hp = gw & 3;
    int h = hp * 2 + (lane >> 4);   // this half-warp's head
    int sub = lane & 15;            // sample index owned by this lane
    int b = q / LEN;

    const int HS[4] = {100, 50, 25, 13};
    const int ST[4] = {0, 10000, 12500, 13125};

    const float* row = oa + (size_t)q * 384;

    // softmax over this head's 16 logits
    float lg = row[256 + h * 16 + sub];
    float m = lg;
    #pragma unroll
    for (int o = 8; o > 0; o >>= 1) m = fmaxf(m, __shfl_xor_sync(0xffffffffu, m, o));
    float e = __expf(lg - m);
    float ssum = e;
    #pragma unroll
    for (int o = 8; o > 0; o >>= 1) ssum += __shfl_xor_sync(0xffffffffu, ssum, o);
    float wnorm = e / ssum;

    // phase 1: per-lane precompute of own sample
    const int l = sub >> 2;
    const int Hl = HS[l];
    const int st = ST[l];
    const float* refp = ref + (size_t)q * 8;
    float rx = refp[l * 2 + 0];
    float ry = refp[l * 2 + 1];
    float2 od = *(const float2*)(row + h * 32 + 2 * sub);

    float x = fmaf(rx, (float)Hl, od.x - 0.5f);
    float y = fmaf(ry, (float)Hl, od.y - 0.5f);
    float x0f = floorf(x), y0f = floorf(y);
    int x0 = (int)x0f, y0 = (int)y0f;
    float dx = x - x0f, dy = y - y0f;

    float mx0 = (x0 >= 0 && x0 < Hl) ? 1.f : 0.f;
    float mx1 = (x0 + 1 >= 0 && x0 + 1 < Hl) ? 1.f : 0.f;
    float my0 = (y0 >= 0 && y0 < Hl) ? 1.f : 0.f;
    float my1 = (y0 + 1 >= 0 && y0 + 1 < Hl) ? 1.f : 0.f;

    int x0c = min(max(x0, 0), Hl - 1);
    int x1c = min(max(x0 + 1, 0), Hl - 1);
    int y0c = min(max(y0, 0), Hl - 1);
    int y1c = min(max(y0 + 1, 0), Hl - 1);

    float wv00 = (1.f - dx) * (1.f - dy) * mx0 * my0 * wnorm;
    float wv10 = dx * (1.f - dy) * mx1 * my0 * wnorm;
    float wv01 = (1.f - dx) * dy * mx0 * my1 * wnorm;
    float wv11 = dx * dy * mx1 * my1 * wnorm;

    int r0 = st + y0c * Hl;
    int r1 = st + y1c * Hl;
    int i00 = r0 + x0c;
    int i10 = r0 + x1c;
    int i01 = r1 + x0c;
    int i11 = r1 + x1c;

    // phase 2: gather loop
    const __half2* vb = (const __half2*)(value + (size_t)b * LEN * 256 + h * 32) + sub;
    const int hbit = lane & 16;

    float accx = 0.f, accy = 0.f;
    #pragma unroll
    for (int s = 0; s < 16; ++s) {
        int srcl = hbit | s;
        int p00 = __shfl_sync(0xffffffffu, i00, srcl);
        int p10 = __shfl_sync(0xffffffffu, i10, srcl);
        int p01 = __shfl_sync(0xffffffffu, i01, srcl);
        int p11 = __shfl_sync(0xffffffffu, i11, srcl);
        float u00 = __shfl_sync(0xffffffffu, wv00, srcl);
        float u10 = __shfl_sync(0xffffffffu, wv10, srcl);
        float u01 = __shfl_sync(0xffffffffu, wv01, srcl);
        float u11 = __shfl_sync(0xffffffffu, wv11, srcl);

        float2 v00 = __half22float2(vb[(size_t)p00 * 128]);
        float2 v10 = __half22float2(vb[(size_t)p10 * 128]);
        float2 v01 = __half22float2(vb[(size_t)p01 * 128]);
        float2 v11 = __half22float2(vb[(size_t)p11 * 128]);

        accx = fmaf(u00, v00.x, accx);
        accy = fmaf(u00, v00.y, accy);
        accx = fmaf(u10, v10.x, accx);
        accy = fmaf(u10, v10.y, accy);
        accx = fmaf(u01, v01.x, accx);
        accy = fmaf(u01, v01.y, accy);
        accx = fmaf(u11, v11.x, accx);
        accy = fmaf(u11, v11.y, accy);
    }
    *(float2*)&out[(size_t)q * 256 + h * 32 + 2 * sub] = make_float2(accx, accy);
}

// ---------------------------------------------------------------------------
// LayerNorm over D=256: one warp per row (unchanged)
// ---------------------------------------------------------------------------
__global__ void ln_kernel(const float* __restrict__ x, const float* __restrict__ g,
                          const float* __restrict__ be, float* __restrict__ y,
                          int nrows) {
    int gtid = blockIdx.x * blockDim.x + threadIdx.x;
    int row = gtid >> 5;
    int lane = gtid & 31;
    if (row >= nrows) return;
    const float* p = x + (size_t)row * 256 + lane * 8;
    float v[8];
    *(float4*)&v[0] = *(const float4*)(p + 0);
    *(float4*)&v[4] = *(const float4*)(p + 4);
    float s = 0.f;
    #pragma unroll
    for (int i = 0; i < 8; ++i) s += v[i];
    #pragma unroll
    for (int o = 16; o > 0; o >>= 1) s += __shfl_xor_sync(0xffffffffu, s, o);
    float mean = s * (1.f / 256.f);
    float vs = 0.f;
    #pragma unroll
    for (int i = 0; i < 8; ++i) { float d = v[i] - mean; vs += d * d; }
    #pragma unroll
    for (int o = 16; o > 0; o >>= 1) vs += __shfl_xor_sync(0xffffffffu, vs, o);
    float rstd = rsqrtf(vs * (1.f / 256.f) + LN_EPS);
    float* q = y + (size_t)row * 256 + lane * 8;
    const float* gp = g + lane * 8;
    const float* bp = be + lane * 8;
    float go[8], bo[8];
    *(float4*)&go[0] = *(const float4*)(gp + 0);
    *(float4*)&go[4] = *(const float4*)(gp + 4);
    *(float4*)&bo[0] = *(const float4*)(bp + 0);
    *(float4*)&bo[4] = *(const float4*)(bp + 4);
    #pragma unroll
    for (int i = 0; i < 8; ++i) v[i] = (v[i] - mean) * rstd * go[i] + bo[i];
    *(float4*)(q + 0) = *(float4*)&v[0];
    *(float4*)(q + 4) = *(float4*)&v[4];
}

// ---------------------------------------------------------------------------
// Host launch
// ---------------------------------------------------------------------------
extern "C" void kernel_launch(void* const* d_in, const int* in_sizes, int n_in,
                              void* d_out, int out_size) {
    const float* src     = (const float*)d_in[0];
    const float* pos     = (const float*)d_in[1];
    const float* refpts  = (const float*)d_in[2];
    const float* W_value = (const float*)d_in[3];
    const float* b_value = (const float*)d_in[4];
    const float* W_off   = (const float*)d_in[5];
    const float* b_off   = (const float*)d_in[6];
    const float* W_attn  = (const float*)d_in[7];
    const float* b_attn  = (const float*)d_in[8];
    const float* W_out   = (const float*)d_in[9];
    const float* b_out   = (const float*)d_in[10];
    const float* W1      = (const float*)d_in[11];
    const float* b1      = (const float*)d_in[12];
    const float* W2      = (const float*)d_in[13];
    const float* b2      = (const float*)d_in[14];
    const float* g1      = (const float*)d_in[15];
    const float* be1     = (const float*)d_in[16];
    const float* g2      = (const float*)d_in[17];
    const float* be2     = (const float*)d_in[18];
    float* out = (float*)d_out;

    void* sp = nullptr;
    cudaGetSymbolAddress(&sp, g_scratch);
    float* base      = (float*)sp;
    float* g_query   = base;
    float* g_valuef  = g_query   + SZ256;
    float* g_oa      = g_valuef  + SZ256;   // merged off+attw [M,384]
    float* g_attnout = g_oa      + SZ384;
    float* g_x1      = g_attnout + SZ256;
    float* g_ln1     = g_x1      + SZ256;
    float* g_x2      = g_ln1     + SZ256;
    float* g_hid     = g_x2      + SZ256;
    float* g_Wcat    = g_hid     + SZ1024;  // [256,384]
    float* g_bcat    = g_Wcat    + 256 * 384;
    __half* g_value_h = (__half*)g_valuef;

    cudaFuncSetAttribute(gemm_tc<false, float>,
                         cudaFuncAttributeMaxDynamicSharedMemorySize, GEMM_SMEM_BYTES);
    cudaFuncSetAttribute(gemm_tc<true, float>,
                         cudaFuncAttributeMaxDynamicSharedMemorySize, GEMM_SMEM_BYTES);
    cudaFuncSetAttribute(gemm_tc<false, __half>,
                         cudaFuncAttributeMaxDynamicSharedMemorySize, GEMM_SMEM_BYTES);

    const int M = TOK;
    const int gy = (M + 127) / 128;   // 208

    // 1) concat weights for merged off+attw GEMM
    {
        int total = 256 * 384;
        concat_kernel<<<(total + 255) / 256, 256>>>(W_off, W_attn, b_off, b_attn,
                                                    g_Wcat, g_bcat);
    }
    // 2) query = src + pos
    {
        int n4 = (int)(SZ256 / 4);
        add_kernel<<<(n4 + 255) / 256, 256>>>(src, pos, g_query, n4);
    }
    // 3) value = src @ Wv + bv  -> fp16
    gemm_tc<false, __half><<<dim3(2, gy), 256, GEMM_SMEM_BYTES>>>(src, W_value, b_value, nullptr, g_value_h, M, 256, 256);
    // 4) oa = query @ Wcat + bcat   (off cols 0..255, attw logits 256..383)
    gemm_tc<false, float><<<dim3(3, gy), 256, GEMM_SMEM_BYTES>>>(g_query, g_Wcat, g_bcat, nullptr, g_oa, M, 384, 256);
    // 5) sampling (+softmax)
    {
        int nthreads = TOK * 4 * 32;
        sample_kernel<<<(nthreads + 255) / 256, 256>>>(g_value_h, g_oa, refpts, g_attnout);
    }
    // 6) x1 = attnout @ Wout + bout + src
    gemm_tc<false, float><<<dim3(2, gy), 256, GEMM_SMEM_BYTES>>>(g_attnout, W_out, b_out, src, g_x1, M, 256, 256);
    // 7) ln1
    {
        int nthreads = TOK * 32;
        ln_kernel<<<(nthreads + 255) / 256, 256>>>(g_x1, g1, be1, g_ln1, TOK);
    }
    // 8) hid = relu(ln1 @ W1 + b1)
    gemm_tc<true, float><<<dim3(8, gy), 256, GEMM_SMEM_BYTES>>>(g_ln1, W1, b1, nullptr, g_hid, M, 1024, 256);
    // 9) x2 = hid @ W2 + b2 + ln1
    gemm_tc<false, float><<<dim3(2, gy), 256, GEMM_SMEM_BYTES>>>(g_hid, W2, b2, g_ln1, g_x2, M, 256, 1024);
    // 10) out = LN(x2)
    {
        int nthreads = TOK * 32;
        ln_kernel<<<(nthreads + 255) / 256, 256>>>(g_x2, g2, be2, out, TOK);
    }
}